// round 13
// baseline (speedup 1.0000x reference)
#include <cuda_runtime.h>
#include <cstdint>

#define B_ 16
#define L_ 256
#define W_ 4
#define N_ 259          // L + W - 1
#define H_ 128
#define EPS_ 1e-6f
#define BN_ (B_ * N_)   // 4144

#define TS_ 96          // attention tile size
#define KC_ 32          // h-chunk (16 f32x2 pairs)
#define HP_ 16          // h-pairs per chunk
#define SSTR2_ 98       // smem row stride in float2 (R10 layout)

// Scratch (no allocations allowed).
__device__ float g_norm[2 * BN_];        // [x1 rows | x2 rows]
__device__ float g_p1[16 * 3 * 320];     // x1_a partials: [b][it][j padded]
__device__ float g_p2[16 * 3 * 320];     // x2_a partials: [b][jt][i padded]
__device__ float g_asum[2 * BN_];        // [x1_a | x2_a]

// att = 1/(1+sqrt(d2)) = r/(1+r), r = rsqrt(d2). Exact identity, one MUFU.RSQ.
__device__ __forceinline__ float att_of_d2(float d2) {
    float r = rsqrtf(d2);
    return __fdividef(r, 1.0f + r);
}

// ---------------------------------------------------------------------------
// 1) Row norms: one warp per (tensor, b, n) row of 128 floats.
// ---------------------------------------------------------------------------
__global__ void norms_kernel(const float* __restrict__ x1,
                             const float* __restrict__ x2) {
    int gt   = blockIdx.x * blockDim.x + threadIdx.x;
    int warp = gt >> 5;
    int lane = gt & 31;
    if (warp >= 2 * BN_) return;
    const float* x = (warp < BN_) ? x1 : x2;
    int row = (warp < BN_) ? warp : warp - BN_;
    float4 v = reinterpret_cast<const float4*>(x + (size_t)row * H_)[lane];
    float s = v.x * v.x + v.y * v.y + v.z * v.z + v.w * v.w;
#pragma unroll
    for (int o = 16; o > 0; o >>= 1) s += __shfl_xor_sync(0xffffffffu, s, o);
    if (lane == 0) g_norm[warp] = s;
}

// ---------------------------------------------------------------------------
// 2) Attention tile 96x96, 6x6 register tile, packed f32x2 FMA inner loop
//    (exact round-10 structure; norms read from g_norm instead of inline).
//    Grid (3,3,16)=(it,jt,b).
// ---------------------------------------------------------------------------
__global__ void __launch_bounds__(256) attn_tile(const float* __restrict__ x1,
                                                 const float* __restrict__ x2) {
    int it = blockIdx.x;            // i tile (x2 rows), 0..2
    int jt = blockIdx.y;            // j tile (x1 rows), 0..2
    int b  = blockIdx.z;            // 0..15

    const float* Ag = x2 + (size_t)b * N_ * H_;   // rows i
    const float* Bg = x1 + (size_t)b * N_ * H_;   // rows j
    const float* nA = g_norm + BN_ + b * N_;      // x2 norms
    const float* nB = g_norm + b * N_;            // x1 norms

    // S2[0]=A operand, S2[1]=B operand; [h-pair][row].
    __shared__ float2 S2[2][HP_][SSTR2_];

    int tid = threadIdx.x;
    int tx = tid & 15;              // j group (6 cols each)
    int ty = tid >> 4;              // i group (6 rows each)
    int i0 = it * TS_;
    int j0 = jt * TS_;

    // Staging geometry: c4 = tid&7 (chunk-invariant float4 slot), r = rbase+32k.
    int c4    = tid & 7;
    int rbase = tid >> 3;           // 0..31

    bool av[3], bv3[3];
    const float4* ap[3];
    const float4* bp[3];
#pragma unroll
    for (int k = 0; k < 3; k++) {
        int ra = i0 + rbase + 32 * k;
        int rb = j0 + rbase + 32 * k;
        av[k]  = (ra < N_);
        bv3[k] = (rb < N_);
        ap[k] = reinterpret_cast<const float4*>(Ag + (size_t)ra * H_ + c4 * 4);
        bp[k] = reinterpret_cast<const float4*>(Bg + (size_t)rb * H_ + c4 * 4);
    }

    // Packed accumulators: acc2[r][c] = (sum over even h, sum over odd h).
    unsigned long long acc2[6][6];
#pragma unroll
    for (int r = 0; r < 6; r++)
#pragma unroll
        for (int c = 0; c < 6; c++) acc2[r][c] = 0ull;

    float4 pA[3], pB[3];
    const float4 z4 = make_float4(0.f, 0.f, 0.f, 0.f);
#pragma unroll
    for (int k = 0; k < 3; k++) {
        pA[k] = av[k]  ? ap[k][0] : z4;
        pB[k] = bv3[k] ? bp[k][0] : z4;
    }

    for (int chunk = 0; chunk < 4; chunk++) {
        __syncthreads();            // previous compute finished reading smem
        // Commit prefetched float4s as two float2 h-pairs each.
#pragma unroll
        for (int k = 0; k < 3; k++) {
            int r = rbase + 32 * k;
            float4 v = pA[k];
            S2[0][c4 * 2 + 0][r] = make_float2(v.x, v.y);
            S2[0][c4 * 2 + 1][r] = make_float2(v.z, v.w);
            v = pB[k];
            S2[1][c4 * 2 + 0][r] = make_float2(v.x, v.y);
            S2[1][c4 * 2 + 1][r] = make_float2(v.z, v.w);
        }
        __syncthreads();
        // Issue next chunk's global loads; latency hidden by the FMA loop.
        if (chunk < 3) {
            int o4 = (chunk + 1) * (KC_ / 4);
#pragma unroll
            for (int k = 0; k < 3; k++) {
                pA[k] = av[k]  ? ap[k][o4] : z4;
                pB[k] = bv3[k] ? bp[k][o4] : z4;
            }
        }

#pragma unroll 4
        for (int h2 = 0; h2 < HP_; h2++) {
            unsigned long long a2[6], b2[6];
#pragma unroll
            for (int r = 0; r < 6; r++)
                a2[r] = *reinterpret_cast<const unsigned long long*>(
                    &S2[0][h2][ty * 6 + r]);
#pragma unroll
            for (int c = 0; c < 6; c++)
                b2[c] = *reinterpret_cast<const unsigned long long*>(
                    &S2[1][h2][tx * 6 + c]);
#pragma unroll
            for (int r = 0; r < 6; r++)
#pragma unroll
                for (int c = 0; c < 6; c++)
                    asm("fma.rn.f32x2 %0, %1, %2, %0;"
                        : "+l"(acc2[r][c]) : "l"(a2[r]), "l"(b2[c]));
        }
    }

    // Epilogue: unpack packed accumulators, attention + both marginals.
    float nb[6];
    bool  jb[6];
#pragma unroll
    for (int c = 0; c < 6; c++) {
        int j = j0 + tx * 6 + c;
        jb[c] = (j < N_);
        nb[c] = jb[c] ? nB[j] : 0.0f;
    }
    float jp[6] = {0.f, 0.f, 0.f, 0.f, 0.f, 0.f};
#pragma unroll
    for (int r = 0; r < 6; r++) {
        int i = i0 + ty * 6 + r;
        float is = 0.0f;
        if (i < N_) {
            float na = nA[i];
#pragma unroll
            for (int c = 0; c < 6; c++) {
                if (jb[c]) {
                    uint2 u = *reinterpret_cast<uint2*>(&acc2[r][c]);
                    float dot = __uint_as_float(u.x) + __uint_as_float(u.y);
                    float d2  = fmaxf(na + nb[c] - 2.0f * dot, 0.0f) + EPS_;
                    float att = att_of_d2(d2);
                    is += att;
                    jp[c] += att;
                }
            }
        }
#pragma unroll
        for (int o = 1; o < 16; o <<= 1)
            is += __shfl_xor_sync(0xffffffffu, is, o);
        if (tx == 0 && i < N_)
            g_p2[(b * 3 + jt) * 320 + i] = is;
    }

    // Cross-warp reduction for per-j (column) sums; reuse S2 as float buffer
    // (needs 16*96 = 6144 floats; S2 holds 2*16*98*2 = 6272 floats).
    __syncthreads();
    float* red = reinterpret_cast<float*>(S2);
#pragma unroll
    for (int c = 0; c < 6; c++)
        red[ty * 96 + tx * 6 + c] = jp[c];
    __syncthreads();
    if (tid < 96) {
        float s = 0.0f;
#pragma unroll
        for (int t = 0; t < 16; t++) s += red[t * 96 + tid];
        int j = j0 + tid;
        if (j < N_) g_p1[(b * 3 + it) * 320 + j] = s;
    }
}

// ---------------------------------------------------------------------------
// 3) Reduce the 3 tile partials per (side, b, q).
// ---------------------------------------------------------------------------
__global__ void reduce_partials_kernel() {
    int i = blockIdx.x * blockDim.x + threadIdx.x;
    if (i >= 2 * BN_) return;
    int s   = i / BN_;
    int rem = i - s * BN_;
    int b   = rem / N_;
    int q   = rem - b * N_;
    const float* p = (s == 0) ? g_p1 : g_p2;
    float sum = 0.0f;
#pragma unroll
    for (int t = 0; t < 3; t++) sum += p[(b * 3 + t) * 320 + q];
    g_asum[i] = sum;
}

// ---------------------------------------------------------------------------
// 4) Windowed weighted-sum epilogue (R6 verbatim: 1 float4/thread, 1024
//    blocks, reads g_asum — measured 5.28us).
// ---------------------------------------------------------------------------
__global__ void wp_kernel(const float* __restrict__ x1,
                          const float* __restrict__ x2,
                          float* __restrict__ out) {
    int i = blockIdx.x * blockDim.x + threadIdx.x;   // over (w,b,l,h4)
    if (i >= 2 * B_ * L_ * (H_ / 4)) return;
    int h4 = i & 31;
    int l  = (i >> 5) & 255;
    int b  = (i >> 13) & 15;
    int w  = i >> 17;
    const float* x = (w ? x2 : x1) + (size_t)b * N_ * H_;
    const float* a = g_asum + w * BN_ + b * N_;
    float4 o = make_float4(0.f, 0.f, 0.f, 0.f);
#pragma unroll
    for (int k = 0; k < W_; k++) {
        float4 v = *reinterpret_cast<const float4*>(x + (size_t)(l + k) * H_ + h4 * 4);
        float wg = a[l + k];
        o.x = fmaf(v.x, wg, o.x);
        o.y = fmaf(v.y, wg, o.y);
        o.z = fmaf(v.z, wg, o.z);
        o.w = fmaf(v.w, wg, o.w);
    }
    reinterpret_cast<float4*>(out)[i] = o;
}

// ---------------------------------------------------------------------------
// Launch order [norms, attn, reduce, wp]: with ncu's `-s 5 -c 1`, launch #6
// is iteration 2's attn_tile — first profile of the dominant kernel.
// ---------------------------------------------------------------------------
extern "C" void kernel_launch(void* const* d_in, const int* in_sizes, int n_in,
                              void* d_out, int out_size) {
    const float* x1 = (const float*)d_in[0];
    const float* x2 = (const float*)d_in[1];
    float* out = (float*)d_out;

    norms_kernel<<<(2 * BN_ * 32 + 255) / 256, 256>>>(x1, x2);

    dim3 grid(3, 3, 16);
    attn_tile<<<grid, 256>>>(x1, x2);

    reduce_partials_kernel<<<(2 * BN_ + 255) / 256, 256>>>();

    wp_kernel<<<(2 * B_ * L_ * 32 + 255) / 256, 256>>>(x1, x2, out);
}

// round 16
// speedup vs baseline: 1.2533x; 1.2533x over previous
#include <cuda_runtime.h>
#include <cstdint>

#define B_ 16
#define L_ 256
#define W_ 4
#define N_ 259          // L + W - 1
#define H_ 128
#define EPS_ 1e-6f
#define BN_ (B_ * N_)   // 4144

#define TS_ 96          // attention tile size
#define KC_ 32          // h-chunk (16 f32x2 pairs)
#define HP_ 16          // h-pairs per chunk
#define SSTR2_ 98       // smem row stride in float2 (word stride 196 -> 2-wf floor)

// Scratch (no allocations allowed).
__device__ float g_p1[16 * 3 * 320];     // x1_a partials: [b][it][j padded]
__device__ float g_p2[16 * 3 * 320];     // x2_a partials: [b][jt][i padded]

// att = 1/(1+sqrt(d2)) = r/(1+r), r = rsqrt(d2). Exact identity, one MUFU.RSQ.
__device__ __forceinline__ float att_of_d2(float d2) {
    float r = rsqrtf(d2);
    return __fdividef(r, 1.0f + r);
}

// ---------------------------------------------------------------------------
// 1) Attention tile 96x96, 6x6 register tile, packed f32x2 FMA inner loop
//    (2 h-positions per instruction -> half the FMA instruction count).
//    Smem layout: [h-pair][row] of float2 = (x[2h2], x[2h2+1]).
//    Pipelined staging + inline norms as in round 9. Grid (3,3,16)=(it,jt,b).
// ---------------------------------------------------------------------------
__global__ void __launch_bounds__(256) attn_tile(const float* __restrict__ x1,
                                                 const float* __restrict__ x2) {
    int it = blockIdx.x;            // i tile (x2 rows), 0..2
    int jt = blockIdx.y;            // j tile (x1 rows), 0..2
    int b  = blockIdx.z;            // 0..15

    const float* Ag = x2 + (size_t)b * N_ * H_;   // rows i
    const float* Bg = x1 + (size_t)b * N_ * H_;   // rows j

    // One contiguous buffer: S2[0]=A operand, S2[1]=B operand.
    __shared__ float2 S2[2][HP_][SSTR2_];
    __shared__ float nAs[TS_];      // |x2_i|^2 for this block's i rows
    __shared__ float nBs[TS_];      // |x1_j|^2 for this block's j rows

    int tid = threadIdx.x;
    int tx = tid & 15;              // j group (6 cols each)
    int ty = tid >> 4;              // i group (6 rows each)
    int i0 = it * TS_;
    int j0 = jt * TS_;

    // Staging geometry: c4 = tid&7 (chunk-invariant float4 slot), r = rbase+32k.
    int c4    = tid & 7;
    int rbase = tid >> 3;           // 0..31

    bool av[3], bv3[3];
    const float4* ap[3];
    const float4* bp[3];
#pragma unroll
    for (int k = 0; k < 3; k++) {
        int ra = i0 + rbase + 32 * k;
        int rb = j0 + rbase + 32 * k;
        av[k]  = (ra < N_);
        bv3[k] = (rb < N_);
        ap[k] = reinterpret_cast<const float4*>(Ag + (size_t)ra * H_ + c4 * 4);
        bp[k] = reinterpret_cast<const float4*>(Bg + (size_t)rb * H_ + c4 * 4);
    }

    // Packed accumulators: acc2[r][c] = (sum over even h, sum over odd h).
    unsigned long long acc2[6][6];
#pragma unroll
    for (int r = 0; r < 6; r++)
#pragma unroll
        for (int c = 0; c < 6; c++) acc2[r][c] = 0ull;

    float napar[3] = {0.f, 0.f, 0.f};
    float nbpar[3] = {0.f, 0.f, 0.f};

    float4 pA[3], pB[3];
    const float4 z4 = make_float4(0.f, 0.f, 0.f, 0.f);
#pragma unroll
    for (int k = 0; k < 3; k++) {
        pA[k] = av[k]  ? ap[k][0] : z4;
        pB[k] = bv3[k] ? bp[k][0] : z4;
    }

    for (int chunk = 0; chunk < 4; chunk++) {
        __syncthreads();            // previous compute finished reading smem
        // Commit prefetched float4s as two float2 h-pairs each (+ norms).
#pragma unroll
        for (int k = 0; k < 3; k++) {
            int r = rbase + 32 * k;
            float4 v = pA[k];
            napar[k] += v.x * v.x + v.y * v.y + v.z * v.z + v.w * v.w;
            S2[0][c4 * 2 + 0][r] = make_float2(v.x, v.y);
            S2[0][c4 * 2 + 1][r] = make_float2(v.z, v.w);
            v = pB[k];
            nbpar[k] += v.x * v.x + v.y * v.y + v.z * v.z + v.w * v.w;
            S2[1][c4 * 2 + 0][r] = make_float2(v.x, v.y);
            S2[1][c4 * 2 + 1][r] = make_float2(v.z, v.w);
        }
        __syncthreads();
        // Issue next chunk's global loads; latency hidden by the FMA loop.
        if (chunk < 3) {
            int o4 = (chunk + 1) * (KC_ / 4);
#pragma unroll
            for (int k = 0; k < 3; k++) {
                pA[k] = av[k]  ? ap[k][o4] : z4;
                pB[k] = bv3[k] ? bp[k][o4] : z4;
            }
        }

#pragma unroll 4
        for (int h2 = 0; h2 < HP_; h2++) {
            unsigned long long a2[6], b2[6];
#pragma unroll
            for (int r = 0; r < 6; r++)
                a2[r] = *reinterpret_cast<const unsigned long long*>(
                    &S2[0][h2][ty * 6 + r]);
#pragma unroll
            for (int c = 0; c < 6; c++)
                b2[c] = *reinterpret_cast<const unsigned long long*>(
                    &S2[1][h2][tx * 6 + c]);
#pragma unroll
            for (int r = 0; r < 6; r++)
#pragma unroll
                for (int c = 0; c < 6; c++)
                    asm("fma.rn.f32x2 %0, %1, %2, %0;"
                        : "+l"(acc2[r][c]) : "l"(a2[r]), "l"(b2[c]));
        }
    }

    // Finish norms: reduce across the 8 lanes sharing each row.
#pragma unroll
    for (int o = 1; o < 8; o <<= 1) {
#pragma unroll
        for (int k = 0; k < 3; k++) {
            napar[k] += __shfl_xor_sync(0xffffffffu, napar[k], o);
            nbpar[k] += __shfl_xor_sync(0xffffffffu, nbpar[k], o);
        }
    }
    if ((tid & 7) == 0) {
#pragma unroll
        for (int k = 0; k < 3; k++) {
            nAs[rbase + 32 * k] = napar[k];
            nBs[rbase + 32 * k] = nbpar[k];
        }
    }
    __syncthreads();

    // Epilogue: unpack packed accumulators, attention + both marginals.
    float nb[6];
    bool  jb[6];
#pragma unroll
    for (int c = 0; c < 6; c++) {
        int j = j0 + tx * 6 + c;
        jb[c] = (j < N_);
        nb[c] = nBs[tx * 6 + c];
    }
    float jp[6] = {0.f, 0.f, 0.f, 0.f, 0.f, 0.f};
#pragma unroll
    for (int r = 0; r < 6; r++) {
        int i = i0 + ty * 6 + r;
        float is = 0.0f;
        if (i < N_) {
            float na = nAs[ty * 6 + r];
#pragma unroll
            for (int c = 0; c < 6; c++) {
                if (jb[c]) {
                    uint2 u = *reinterpret_cast<uint2*>(&acc2[r][c]);
                    float dot = __uint_as_float(u.x) + __uint_as_float(u.y);
                    float d2  = fmaxf(na + nb[c] - 2.0f * dot, 0.0f) + EPS_;
                    float att = att_of_d2(d2);
                    is += att;
                    jp[c] += att;
                }
            }
        }
#pragma unroll
        for (int o = 1; o < 16; o <<= 1)
            is += __shfl_xor_sync(0xffffffffu, is, o);
        if (tx == 0 && i < N_)
            g_p2[(b * 3 + jt) * 320 + i] = is;
    }

    // Cross-warp reduction for per-j (column) sums; reuse S2 as float buffer
    // (needs 16*96 = 6144 floats; S2 holds 2*16*98*2 = 6272 floats).
    __syncthreads();
    float* red = reinterpret_cast<float*>(S2);
#pragma unroll
    for (int c = 0; c < 6; c++)
        red[ty * 96 + tx * 6 + c] = jp[c];
    __syncthreads();
    if (tid < 96) {
        float s = 0.0f;
#pragma unroll
        for (int t = 0; t < 16; t++) s += red[t * 96 + tid];
        int j = j0 + tid;
        if (j < N_) g_p1[(b * 3 + it) * 320 + j] = s;
    }
}

// ---------------------------------------------------------------------------
// 2) Windowed weighted-sum epilogue with the 3-slot partial reduction fused
//    (unchanged from round 9 — measured stable).
// ---------------------------------------------------------------------------
__global__ void __launch_bounds__(256) wp_kernel(const float* __restrict__ x1,
                                                 const float* __restrict__ x2,
                                                 float* __restrict__ out) {
    __shared__ float sa[12];
    int bi   = blockIdx.x;          // 0..1023
    int lblk = bi & 31;
    int b    = (bi >> 5) & 15;
    int w    = bi >> 9;
    int tid  = threadIdx.x;
    int l0   = lblk * 8;

    if (tid < 11) {
        const float* p = (w ? g_p2 : g_p1) + b * 3 * 320;
        int q = l0 + tid;           // max 248+10 = 258 < N_
        sa[tid] = p[q] + p[320 + q] + p[640 + q];
    }
    __syncthreads();

    int h4 = tid & 31;
    int dl = tid >> 5;
    int l  = l0 + dl;
    const float* x = (w ? x2 : x1) + (size_t)b * N_ * H_ + h4 * 4;

    float4 o = make_float4(0.f, 0.f, 0.f, 0.f);
#pragma unroll
    for (int k = 0; k < W_; k++) {
        float4 v = *reinterpret_cast<const float4*>(x + (size_t)(l + k) * H_);
        float wg = sa[dl + k];
        o.x = fmaf(v.x, wg, o.x);
        o.y = fmaf(v.y, wg, o.y);
        o.z = fmaf(v.z, wg, o.z);
        o.w = fmaf(v.w, wg, o.w);
    }
    size_t oi = ((size_t)(w * 16 + b) * 256 + l) * 32 + h4;
    reinterpret_cast<float4*>(out)[oi] = o;
}

// ---------------------------------------------------------------------------
extern "C" void kernel_launch(void* const* d_in, const int* in_sizes, int n_in,
                              void* d_out, int out_size) {
    const float* x1 = (const float*)d_in[0];
    const float* x2 = (const float*)d_in[1];
    float* out = (float*)d_out;

    dim3 grid(3, 3, 16);
    attn_tile<<<grid, 256>>>(x1, x2);

    wp_kernel<<<1024, 256>>>(x1, x2, out);
}